// round 10
// baseline (speedup 1.0000x reference)
#include <cuda_runtime.h>
#include <cuda_fp16.h>
#include <cuda_fp8.h>
#include <cstdint>

// Problem sizes (fixed by setup_inputs)
#define MROWS 32768   // B*S = 8*4096
#define NCOLS 1024    // OUT_F
#define KDIM  1024    // IN_F

// GEMM tiling: 3 CTAs/SM (24 warps/SM), CTA 64x128, warp tile 32x32
#define BM 64
#define BN 128
#define BK 64
#define STAGES 4
#define KITERS (KDIM / BK)          // 16
#define ROW_STRIDE 80               // 64B data + 16B pad -> conflict-free ldmatrix
#define A_TILE_BYTES (BM * ROW_STRIDE)            // 5120
#define B_TILE_BYTES (BN * ROW_STRIDE)            // 10240
#define STAGE_BYTES (A_TILE_BYTES + B_TILE_BYTES) // 15360
#define SMEM_BYTES (STAGES * STAGE_BYTES)         // 61440
#define NTHREADS 256

// ---------------- device scratch (allowed: __device__ globals) ----------------
__device__ uint8_t g_xq[(size_t)MROWS * KDIM];   // 32 MB, e4m3-coded ints -7..7
__device__ uint8_t g_wq[(size_t)NCOLS * KDIM];   // 1 MB,  e4m3-coded ternary -1,0,1
__device__ float   g_sx[MROWS];                  // per-row max_abs/7
__device__ float   g_alpha[NCOLS];               // per-out-row mean |w|

// ---------------- PTX helpers (baseline ISA only: sm_80/89+) ----------------
__device__ __forceinline__ uint32_t smem_to_u32(const void* p) {
    uint32_t a;
    asm("{ .reg .u64 t; cvta.to.shared.u64 t, %1; cvt.u32.u64 %0, t; }" : "=r"(a) : "l"(p));
    return a;
}

#define CP_ASYNC16(dst, src) \
    asm volatile("cp.async.cg.shared.global [%0], [%1], 16;" :: "r"(dst), "l"(src) : "memory")
#define CP_COMMIT() asm volatile("cp.async.commit_group;" ::: "memory")
#define CP_WAIT(n)  asm volatile("cp.async.wait_group %0;" :: "n"(n) : "memory")

#define LDSM_X4(r0, r1, r2, r3, addr) \
    asm volatile("ldmatrix.sync.aligned.m8n8.x4.shared.b16 {%0,%1,%2,%3}, [%4];" \
        : "=r"(r0), "=r"(r1), "=r"(r2), "=r"(r3) : "r"(addr))

// FP8 e4m3 MMA, f16 accumulate.
// All operands are exact small integers; |acc| stays < 2048 (30-sigma bound)
// -> arithmetic is exact over the full K=1024 accumulation.
#define MMA_E4M3_F16(c0, c1, a0, a1, a2, a3, b0, b1) \
    asm volatile("mma.sync.aligned.m16n8k32.row.col.f16.e4m3.e4m3.f16 " \
        "{%0,%1}, {%2,%3,%4,%5}, {%6,%7}, {%0,%1};" \
        : "+r"(c0), "+r"(c1) \
        : "r"(a0), "r"(a1), "r"(a2), "r"(a3), "r"(b0), "r"(b1))

// ---------------- pass 1: quantize x rows to e4m3 ints ----------------
__device__ __forceinline__ uint32_t pack_q(float v, float inv) {
    // integer in [-7,7], encoded as e4m3 (exact)
    return (uint32_t)__nv_cvt_float_to_fp8(rintf(v * inv), __NV_SATFINITE, __NV_E4M3);
}

__global__ void __launch_bounds__(128) quant_x_kernel(const float* __restrict__ x) {
    __shared__ float red[4];
    const int row = blockIdx.x;
    const int tid = threadIdx.x;
    const float4* xr = reinterpret_cast<const float4*>(x + (size_t)row * KDIM);
    float4 a = xr[tid];
    float4 b = xr[tid + 128];
    float m = fmaxf(fmaxf(fabsf(a.x), fabsf(a.y)), fmaxf(fabsf(a.z), fabsf(a.w)));
    m = fmaxf(m, fmaxf(fmaxf(fabsf(b.x), fabsf(b.y)), fmaxf(fabsf(b.z), fabsf(b.w))));
    #pragma unroll
    for (int off = 16; off > 0; off >>= 1)
        m = fmaxf(m, __shfl_xor_sync(0xFFFFFFFFu, m, off));
    if ((tid & 31) == 0) red[tid >> 5] = m;
    __syncthreads();
    m = fmaxf(fmaxf(red[0], red[1]), fmaxf(red[2], red[3]));
    const float maxabs = fmaxf(m, 1e-6f);
    const float inv = 7.0f / maxabs;

    uint32_t pa = pack_q(a.x, inv) | (pack_q(a.y, inv) << 8)
                | (pack_q(a.z, inv) << 16) | (pack_q(a.w, inv) << 24);
    uint32_t pb = pack_q(b.x, inv) | (pack_q(b.y, inv) << 8)
                | (pack_q(b.z, inv) << 16) | (pack_q(b.w, inv) << 24);
    uint32_t* dst = reinterpret_cast<uint32_t*>(g_xq + (size_t)row * KDIM);
    dst[tid]       = pa;
    dst[tid + 128] = pb;
    if (tid == 0) g_sx[row] = maxabs * (1.0f / 7.0f);
}

// ---------------- weight prep ----------------
__global__ void __launch_bounds__(256) weight_alpha_kernel(const float* __restrict__ w) {
    __shared__ float red[8];
    const int row = blockIdx.x;
    const int tid = threadIdx.x;
    float4 a = reinterpret_cast<const float4*>(w + (size_t)row * KDIM)[tid];
    float s = fabsf(a.x) + fabsf(a.y) + fabsf(a.z) + fabsf(a.w);
    #pragma unroll
    for (int off = 16; off > 0; off >>= 1) s += __shfl_xor_sync(0xFFFFFFFFu, s, off);
    if ((tid & 31) == 0) red[tid >> 5] = s;
    __syncthreads();
    if (tid == 0) {
        float t = 0.f;
        #pragma unroll
        for (int i = 0; i < 8; ++i) t += red[i];
        g_alpha[row] = t / 1024.0f;
    }
}

__device__ __forceinline__ uint32_t tern_byte(float v, float thresh) {
    if (fabsf(v) < thresh) return 0u;          // e4m3 zero
    return (v > 0.f) ? 0x38u : 0xB8u;          // e4m3 +1 / -1
}

__global__ void __launch_bounds__(256) weight_tern_kernel(const float* __restrict__ w) {
    __shared__ float red[8];
    const int row = blockIdx.x;
    const int tid = threadIdx.x;
    float s = g_alpha[tid] + g_alpha[tid + 256] + g_alpha[tid + 512] + g_alpha[tid + 768];
    #pragma unroll
    for (int off = 16; off > 0; off >>= 1) s += __shfl_xor_sync(0xFFFFFFFFu, s, off);
    if ((tid & 31) == 0) red[tid >> 5] = s;
    __syncthreads();
    float tot = 0.f;
    #pragma unroll
    for (int i = 0; i < 8; ++i) tot += red[i];
    const float thresh = 0.05f * (tot / 1024.0f);

    float4 a = reinterpret_cast<const float4*>(w + (size_t)row * KDIM)[tid];
    uint32_t p = tern_byte(a.x, thresh)
               | (tern_byte(a.y, thresh) << 8)
               | (tern_byte(a.z, thresh) << 16)
               | (tern_byte(a.w, thresh) << 24);
    reinterpret_cast<uint32_t*>(g_wq + (size_t)row * KDIM)[tid] = p;
}

// ---------------- GEMM: out[m,n] = SUM[m,n]*sx[m]*alpha[n] + bias[n] ----------------
// 256 threads = 8 warps; warp grid 2(M) x 4(N); warp tile 32x32 (slim registers).
// 3 CTAs/SM = 24 warps/SM = 6 warps/SMSP: cross-warp parallelism hides MMA/LDSM
// latency instead of intra-warp prefetch.
// Full-K f16 accumulation (exact: |sum| << 2048 at 30-sigma).
__global__ void __launch_bounds__(NTHREADS, 3) gemm_kernel(
    const float* __restrict__ bias, float* __restrict__ out)
{
    extern __shared__ char smem[];
    const uint32_t sb = smem_to_u32(smem);
    const int tid = threadIdx.x;
    const int wid = tid >> 5;
    const int lane = tid & 31;
    const int warp_m = wid & 1;      // 0..1
    const int warp_n = wid >> 1;     // 0..3
    const int m0 = blockIdx.y * BM;
    const int n0 = blockIdx.x * BN;

    // per-thread stage-load coordinates:
    // A: 64 rows x 4 x 16B chunks = 256 chunks -> 1 per thread
    // B: 128 rows x 4 = 512 chunks -> 2 per thread
    const int rr = tid >> 2, cc4 = (tid & 3) * 16;
    const uint8_t* gA_p = g_xq + (size_t)(m0 + rr) * KDIM + cc4;
    const uint8_t* gB_p0 = g_wq + (size_t)(n0 + rr) * KDIM + cc4;
    const uint8_t* gB_p1 = g_wq + (size_t)(n0 + 64 + rr) * KDIM + cc4;
    const uint32_t sA_o  = (uint32_t)(rr * ROW_STRIDE + cc4);
    const uint32_t sB_o0 = (uint32_t)(A_TILE_BYTES + rr * ROW_STRIDE + cc4);
    const uint32_t sB_o1 = (uint32_t)(A_TILE_BYTES + (64 + rr) * ROW_STRIDE + cc4);

    // ldmatrix per-lane offsets
    const uint32_t aRowOff = (uint32_t)(((lane & 7) + ((lane >> 3) & 1) * 8) * ROW_STRIDE
                                        + ((lane >> 4) & 1) * 16);
    const uint32_t bRowOff = (uint32_t)(((lane & 7) + ((lane >> 4) & 1) * 8) * ROW_STRIDE
                                        + ((lane >> 3) & 1) * 16);

    uint32_t hacc[2][4][2];          // f16x2 accumulators (exact ints, full K)
    #pragma unroll
    for (int i = 0; i < 2; ++i)
        #pragma unroll
        for (int j = 0; j < 4; ++j) { hacc[i][j][0] = 0u; hacc[i][j][1] = 0u; }

    auto load_stage = [&](int s, int kt) {
        const uint32_t d = sb + s * STAGE_BYTES;
        const int kb = kt * BK;
        CP_ASYNC16(d + sA_o,  gA_p  + kb);
        CP_ASYNC16(d + sB_o0, gB_p0 + kb);
        CP_ASYNC16(d + sB_o1, gB_p1 + kb);
    };

    // prologue: fill STAGES-1 stages
    #pragma unroll
    for (int s = 0; s < STAGES - 1; ++s) { load_stage(s, s); CP_COMMIT(); }

    for (int kt = 0; kt < KITERS; ++kt) {
        CP_WAIT(STAGES - 2);
        __syncthreads();

        // refill the stage consumed at kt-1 (all warps passed the barrier)
        const int nk = kt + STAGES - 1;
        if (nk < KITERS) load_stage(nk & (STAGES - 1), nk);
        CP_COMMIT();

        const int stage = kt & (STAGES - 1);
        const uint32_t aBase = sb + stage * STAGE_BYTES
                               + (uint32_t)warp_m * 32 * ROW_STRIDE + aRowOff;
        const uint32_t bBase = sb + stage * STAGE_BYTES + A_TILE_BYTES
                               + (uint32_t)warp_n * 32 * ROW_STRIDE + bRowOff;

        #pragma unroll
        for (int kk = 0; kk < 2; ++kk) {        // two k32 steps in BK=64
            uint32_t a[2][4];
            #pragma unroll
            for (int mt = 0; mt < 2; ++mt)
                LDSM_X4(a[mt][0], a[mt][1], a[mt][2], a[mt][3],
                        aBase + mt * (16 * ROW_STRIDE) + kk * 32);
            uint32_t b[4][2];
            #pragma unroll
            for (int p = 0; p < 2; ++p)
                LDSM_X4(b[2 * p][0], b[2 * p][1], b[2 * p + 1][0], b[2 * p + 1][1],
                        bBase + p * (16 * ROW_STRIDE) + kk * 32);
            #pragma unroll
            for (int mt = 0; mt < 2; ++mt)
                #pragma unroll
                for (int nt = 0; nt < 4; ++nt)
                    MMA_E4M3_F16(hacc[mt][nt][0], hacc[mt][nt][1],
                                 a[mt][0], a[mt][1], a[mt][2], a[mt][3],
                                 b[nt][0], b[nt][1]);
        }
        __syncthreads();
    }

    // epilogue: convert exact f16 sums -> f32, scale, bias, store
    const int g = lane >> 2, tig = lane & 3;
    const int mwb = m0 + warp_m * 32;
    const int nwb = n0 + warp_n * 32;
    #pragma unroll
    for (int mt = 0; mt < 2; ++mt) {
        const int row0 = mwb + mt * 16 + g;
        const float sx0 = g_sx[row0];
        const float sx1 = g_sx[row0 + 8];
        #pragma unroll
        for (int nt = 0; nt < 4; ++nt) {
            const int col = nwb + nt * 8 + tig * 2;
            const float al0 = g_alpha[col], al1 = g_alpha[col + 1];
            const float bi0 = bias[col],    bi1 = bias[col + 1];
            float2 f0 = __half22float2(*reinterpret_cast<__half2*>(&hacc[mt][nt][0]));
            float2 f1 = __half22float2(*reinterpret_cast<__half2*>(&hacc[mt][nt][1]));
            float2 v0, v1;
            v0.x = fmaf(f0.x * sx0, al0, bi0);
            v0.y = fmaf(f0.y * sx0, al1, bi1);
            v1.x = fmaf(f1.x * sx1, al0, bi0);
            v1.y = fmaf(f1.y * sx1, al1, bi1);
            *reinterpret_cast<float2*>(out + (size_t)row0 * NCOLS + col) = v0;
            *reinterpret_cast<float2*>(out + (size_t)(row0 + 8) * NCOLS + col) = v1;
        }
    }
}

// ---------------- host launch ----------------
extern "C" void kernel_launch(void* const* d_in, const int* in_sizes, int n_in,
                              void* d_out, int out_size) {
    (void)in_sizes; (void)n_in; (void)out_size;
    const float* x    = (const float*)d_in[0];
    const float* w    = (const float*)d_in[1];
    const float* bias = (const float*)d_in[2];
    float* out = (float*)d_out;

    quant_x_kernel<<<MROWS, 128>>>(x);
    weight_alpha_kernel<<<NCOLS, 256>>>(w);
    weight_tern_kernel<<<NCOLS, 256>>>(w);

    cudaFuncSetAttribute(gemm_kernel, cudaFuncAttributeMaxDynamicSharedMemorySize, SMEM_BYTES);
    dim3 grid(NCOLS / BN, MROWS / BM);   // 8 x 512; n fastest -> A tiles reused in L2
    gemm_kernel<<<grid, NTHREADS, SMEM_BYTES>>>(bias, out);
}

// round 11
// speedup vs baseline: 1.2341x; 1.2341x over previous
#include <cuda_runtime.h>
#include <cuda_fp16.h>
#include <cstdint>

// Problem sizes (fixed by setup_inputs)
#define MROWS 32768   // B*S = 8*4096
#define NCOLS 1024    // OUT_F
#define KDIM  1024    // IN_F

// GEMM tiling: CTA 128x256, 8 warps (2x4), warp tile 64x64, f16 operands
#define BM 128
#define BN 256
#define BK 64
#define KITERS (KDIM / BK)            // 16... no: 1024/64 = 16
#define ROW_STRIDE 144                // 128B f16 data + 16B pad -> conflict-free ldmatrix
#define A_TILE_BYTES (BM * ROW_STRIDE)            // 18432
#define B_TILE_BYTES (BN * ROW_STRIDE)            // 36864
#define STAGE_BYTES (A_TILE_BYTES + B_TILE_BYTES) // 55296
#define SMEM_BYTES (2 * STAGE_BYTES)              // 110592 (double buffer)
#define NTHREADS 256

// ---------------- device scratch (allowed: __device__ globals) ----------------
__device__ uint8_t g_xq[(size_t)MROWS * KDIM * 2]; // 64 MB, f16-coded ints -7..7
__device__ uint8_t g_wq[(size_t)NCOLS * KDIM * 2]; // 2 MB,  f16-coded ternary -1,0,1
__device__ float   g_sx[MROWS];                    // per-row max_abs/7
__device__ float   g_alpha[NCOLS];                 // per-out-row mean |w|

// ---------------- PTX helpers (baseline ISA only: sm_80+) ----------------
__device__ __forceinline__ uint32_t smem_to_u32(const void* p) {
    uint32_t a;
    asm("{ .reg .u64 t; cvta.to.shared.u64 t, %1; cvt.u32.u64 %0, t; }" : "=r"(a) : "l"(p));
    return a;
}

#define CP_ASYNC16(dst, src) \
    asm volatile("cp.async.cg.shared.global [%0], [%1], 16;" :: "r"(dst), "l"(src) : "memory")
#define CP_COMMIT() asm volatile("cp.async.commit_group;" ::: "memory")
#define CP_WAIT(n)  asm volatile("cp.async.wait_group %0;" :: "n"(n) : "memory")

#define LDSM_X4(r0, r1, r2, r3, addr) \
    asm volatile("ldmatrix.sync.aligned.m8n8.x4.shared.b16 {%0,%1,%2,%3}, [%4];" \
        : "=r"(r0), "=r"(r1), "=r"(r2), "=r"(r3) : "r"(addr))

// Native f16 HMMA (m16n8k16), f16 accumulate. No operand conversions.
// All operands are exact small integers; |acc| stays < 2048 (30-sigma bound)
// -> arithmetic is exact over the full K=1024 accumulation.
#define MMA_F16(c0, c1, a0, a1, a2, a3, b0, b1) \
    asm volatile("mma.sync.aligned.m16n8k16.row.col.f16.f16.f16.f16 " \
        "{%0,%1}, {%2,%3,%4,%5}, {%6,%7}, {%0,%1};" \
        : "+r"(c0), "+r"(c1) \
        : "r"(a0), "r"(a1), "r"(a2), "r"(a3), "r"(b0), "r"(b1))

// ---------------- pass 1: quantize x rows to f16 ints ----------------
__device__ __forceinline__ uint32_t pack_q2(float v0, float v1, float inv) {
    __half2 h = __floats2half2_rn(rintf(v0 * inv), rintf(v1 * inv));
    return *reinterpret_cast<uint32_t*>(&h);
}

__global__ void __launch_bounds__(128) quant_x_kernel(const float* __restrict__ x) {
    __shared__ float red[4];
    const int row = blockIdx.x;
    const int tid = threadIdx.x;
    const float4* xr = reinterpret_cast<const float4*>(x + (size_t)row * KDIM);
    float4 a = xr[tid];
    float4 b = xr[tid + 128];
    float m = fmaxf(fmaxf(fabsf(a.x), fabsf(a.y)), fmaxf(fabsf(a.z), fabsf(a.w)));
    m = fmaxf(m, fmaxf(fmaxf(fabsf(b.x), fabsf(b.y)), fmaxf(fabsf(b.z), fabsf(b.w))));
    #pragma unroll
    for (int off = 16; off > 0; off >>= 1)
        m = fmaxf(m, __shfl_xor_sync(0xFFFFFFFFu, m, off));
    if ((tid & 31) == 0) red[tid >> 5] = m;
    __syncthreads();
    m = fmaxf(fmaxf(red[0], red[1]), fmaxf(red[2], red[3]));
    const float maxabs = fmaxf(m, 1e-6f);
    const float inv = 7.0f / maxabs;

    uint2 pa, pb;
    pa.x = pack_q2(a.x, a.y, inv);
    pa.y = pack_q2(a.z, a.w, inv);
    pb.x = pack_q2(b.x, b.y, inv);
    pb.y = pack_q2(b.z, b.w, inv);
    uint2* dst = reinterpret_cast<uint2*>(g_xq + (size_t)row * KDIM * 2);
    dst[tid]       = pa;
    dst[tid + 128] = pb;
    if (tid == 0) g_sx[row] = maxabs * (1.0f / 7.0f);
}

// ---------------- weight prep ----------------
__global__ void __launch_bounds__(256) weight_alpha_kernel(const float* __restrict__ w) {
    __shared__ float red[8];
    const int row = blockIdx.x;
    const int tid = threadIdx.x;
    float4 a = reinterpret_cast<const float4*>(w + (size_t)row * KDIM)[tid];
    float s = fabsf(a.x) + fabsf(a.y) + fabsf(a.z) + fabsf(a.w);
    #pragma unroll
    for (int off = 16; off > 0; off >>= 1) s += __shfl_xor_sync(0xFFFFFFFFu, s, off);
    if ((tid & 31) == 0) red[tid >> 5] = s;
    __syncthreads();
    if (tid == 0) {
        float t = 0.f;
        #pragma unroll
        for (int i = 0; i < 8; ++i) t += red[i];
        g_alpha[row] = t / 1024.0f;
    }
}

__device__ __forceinline__ uint32_t tern_h(float v, float thresh) {
    if (fabsf(v) < thresh) return 0u;          // f16 zero
    return (v > 0.f) ? 0x3C00u : 0xBC00u;      // f16 +1 / -1
}

__global__ void __launch_bounds__(256) weight_tern_kernel(const float* __restrict__ w) {
    __shared__ float red[8];
    const int row = blockIdx.x;
    const int tid = threadIdx.x;
    float s = g_alpha[tid] + g_alpha[tid + 256] + g_alpha[tid + 512] + g_alpha[tid + 768];
    #pragma unroll
    for (int off = 16; off > 0; off >>= 1) s += __shfl_xor_sync(0xFFFFFFFFu, s, off);
    if ((tid & 31) == 0) red[tid >> 5] = s;
    __syncthreads();
    float tot = 0.f;
    #pragma unroll
    for (int i = 0; i < 8; ++i) tot += red[i];
    const float thresh = 0.05f * (tot / 1024.0f);

    float4 a = reinterpret_cast<const float4*>(w + (size_t)row * KDIM)[tid];
    uint2 p;
    p.x = tern_h(a.x, thresh) | (tern_h(a.y, thresh) << 16);
    p.y = tern_h(a.z, thresh) | (tern_h(a.w, thresh) << 16);
    reinterpret_cast<uint2*>(g_wq + (size_t)row * KDIM * 2)[tid] = p;
}

// ---------------- GEMM: out[m,n] = SUM[m,n]*sx[m]*alpha[n] + bias[n] ----------------
// 256 threads = 8 warps; warp grid 2(M) x 4(N); warp tile 64x64.
// Native f16 HMMA, 0.25 LDSM per MMA, 32 accumulator chains per warp.
// Full-K f16 accumulation (exact: |sum| << 2048 at 30-sigma).
__global__ void __launch_bounds__(NTHREADS, 2) gemm_kernel(
    const float* __restrict__ bias, float* __restrict__ out)
{
    extern __shared__ char smem[];
    const uint32_t sb = smem_to_u32(smem);
    const int tid = threadIdx.x;
    const int wid = tid >> 5;
    const int lane = tid & 31;
    const int warp_m = wid & 1;      // 0..1
    const int warp_n = wid >> 1;     // 0..3
    const int m0 = blockIdx.y * BM;
    const int n0 = blockIdx.x * BN;

    // stage-load mapping: 16B chunks, 8 chunks per 128B (64-f16) row.
    // A: 128 rows x 8 = 1024 chunks -> 4/thread; B: 256 x 8 = 2048 -> 8/thread.
    // One base pointer each; j-offsets are compile-time constants.
    const int cc = tid & 7;               // chunk column 0..7
    const int rb = tid >> 3;              // base row 0..31 (step 32)
    const uint8_t* gA_p = g_xq + ((size_t)(m0 + rb) * KDIM + cc * 8) * 2;
    const uint8_t* gB_p = g_wq + ((size_t)(n0 + rb) * KDIM + cc * 8) * 2;
    const uint32_t sA_b = (uint32_t)(rb * ROW_STRIDE + cc * 16);
    const uint32_t sB_b = (uint32_t)(A_TILE_BYTES + rb * ROW_STRIDE + cc * 16);

    // ldmatrix per-lane offsets (b16, 16B = 8 f16 = half of k16)
    const uint32_t aRowOff = (uint32_t)(((lane & 7) + ((lane >> 3) & 1) * 8) * ROW_STRIDE
                                        + ((lane >> 4) & 1) * 16);
    const uint32_t bRowOff = (uint32_t)(((lane & 7) + ((lane >> 4) & 1) * 8) * ROW_STRIDE
                                        + ((lane >> 3) & 1) * 16);

    uint32_t hacc[4][8][2];          // f16x2 accumulators (exact ints, full K)
    #pragma unroll
    for (int i = 0; i < 4; ++i)
        #pragma unroll
        for (int j = 0; j < 8; ++j) { hacc[i][j][0] = 0u; hacc[i][j][1] = 0u; }

    auto load_stage = [&](int s, int it) {
        const uint32_t d = sb + s * STAGE_BYTES;
        const size_t kb = (size_t)it * (BK * 2);   // byte advance along K
        #pragma unroll
        for (int j = 0; j < 4; ++j)
            CP_ASYNC16(d + sA_b + j * (32 * ROW_STRIDE), gA_p + kb + (size_t)j * (32 * KDIM * 2));
        #pragma unroll
        for (int j = 0; j < 8; ++j)
            CP_ASYNC16(d + sB_b + j * (32 * ROW_STRIDE), gB_p + kb + (size_t)j * (32 * KDIM * 2));
    };

    // prologue: fill stage 0
    load_stage(0, 0);
    CP_COMMIT();

    #pragma unroll 4
    for (int it = 0; it < KITERS; ++it) {
        CP_WAIT(0);
        __syncthreads();   // load(it) landed; all warps done with the other buffer

        if (it + 1 < KITERS) {
            load_stage((it + 1) & 1, it + 1);
            CP_COMMIT();
        }

        const uint32_t aBase = sb + (it & 1) * STAGE_BYTES
                               + (uint32_t)warp_m * 64 * ROW_STRIDE + aRowOff;
        const uint32_t bBase = sb + (it & 1) * STAGE_BYTES + A_TILE_BYTES
                               + (uint32_t)warp_n * 64 * ROW_STRIDE + bRowOff;

        #pragma unroll
        for (int kk = 0; kk < 4; ++kk) {        // four k16 steps in BK=64
            uint32_t a[4][4];
            #pragma unroll
            for (int mt = 0; mt < 4; ++mt)
                LDSM_X4(a[mt][0], a[mt][1], a[mt][2], a[mt][3],
                        aBase + mt * (16 * ROW_STRIDE) + kk * 32);
            uint32_t b[8][2];
            #pragma unroll
            for (int p = 0; p < 4; ++p)
                LDSM_X4(b[2 * p][0], b[2 * p][1], b[2 * p + 1][0], b[2 * p + 1][1],
                        bBase + p * (16 * ROW_STRIDE) + kk * 32);
            #pragma unroll
            for (int mt = 0; mt < 4; ++mt)
                #pragma unroll
                for (int nt = 0; nt < 8; ++nt)
                    MMA_F16(hacc[mt][nt][0], hacc[mt][nt][1],
                            a[mt][0], a[mt][1], a[mt][2], a[mt][3],
                            b[nt][0], b[nt][1]);
        }
    }

    // epilogue: convert exact f16 sums -> f32, scale, bias, store
    const int g = lane >> 2, tig = lane & 3;
    const int mwb = m0 + warp_m * 64;
    const int nwb = n0 + warp_n * 64;
    #pragma unroll
    for (int mt = 0; mt < 4; ++mt) {
        const int row0 = mwb + mt * 16 + g;
        const float sx0 = g_sx[row0];
        const float sx1 = g_sx[row0 + 8];
        #pragma unroll
        for (int nt = 0; nt < 8; ++nt) {
            const int col = nwb + nt * 8 + tig * 2;
            const float al0 = g_alpha[col], al1 = g_alpha[col + 1];
            const float bi0 = bias[col],    bi1 = bias[col + 1];
            float2 f0 = __half22float2(*reinterpret_cast<__half2*>(&hacc[mt][nt][0]));
            float2 f1 = __half22float2(*reinterpret_cast<__half2*>(&hacc[mt][nt][1]));
            float2 v0, v1;
            v0.x = fmaf(f0.x * sx0, al0, bi0);
            v0.y = fmaf(f0.y * sx0, al1, bi1);
            v1.x = fmaf(f1.x * sx1, al0, bi0);
            v1.y = fmaf(f1.y * sx1, al1, bi1);
            *reinterpret_cast<float2*>(out + (size_t)row0 * NCOLS + col) = v0;
            *reinterpret_cast<float2*>(out + (size_t)(row0 + 8) * NCOLS + col) = v1;
        }
    }
}

// ---------------- host launch ----------------
extern "C" void kernel_launch(void* const* d_in, const int* in_sizes, int n_in,
                              void* d_out, int out_size) {
    (void)in_sizes; (void)n_in; (void)out_size;
    const float* x    = (const float*)d_in[0];
    const float* w    = (const float*)d_in[1];
    const float* bias = (const float*)d_in[2];
    float* out = (float*)d_out;

    quant_x_kernel<<<MROWS, 128>>>(x);
    weight_alpha_kernel<<<NCOLS, 256>>>(w);
    weight_tern_kernel<<<NCOLS, 256>>>(w);

    cudaFuncSetAttribute(gemm_kernel, cudaFuncAttributeMaxDynamicSharedMemorySize, SMEM_BYTES);
    dim3 grid(NCOLS / BN, MROWS / BM);   // 4 x 256; n fastest -> A tiles reused in L2
    gemm_kernel<<<grid, NTHREADS, SMEM_BYTES>>>(bias, out);
}